// round 4
// baseline (speedup 1.0000x reference)
#include <cuda_runtime.h>
#include <math.h>

#define Bq 4
#define Nq 1024
#define Cq 256
#define Hq 60
#define Wq 80
#define HWq (Hq*Wq)          // 4800
#define GS 8.0f
#define NUM_NEG 4
#define D1 4

// ---------------- scratch (device globals; no allocs allowed) ----------------
__device__ float g_kd[Bq*Nq*Cq];            // normalized kp1 descriptors  (4 MB)
__device__ float g_d2t[Bq*HWq*Cq];          // raw desc2 transposed [b][m][c] (19.6 MB)
__device__ float g_inorm[Bq*HWq];           // 1/sqrt(ss+eps) per cell
__device__ float g_pos[Bq*Nq];
__device__ int   g_nbr[Bq*Nq*16];           // 16 penalized cell ids per row
__device__ float g_sim[Bq*Nq*HWq];          // sim matrix (78.6 MB)
__device__ float g_rowloss[Bq*Nq];

// ---------------- helpers ----------------
__device__ __forceinline__ float block_sum256(float v, float* red) {
    int t = threadIdx.x;
    red[t] = v; __syncthreads();
    #pragma unroll
    for (int s = 128; s > 0; s >>= 1) {
        if (t < s) red[t] += red[t + s];
        __syncthreads();
    }
    float r = red[0]; __syncthreads();
    return r;
}

// 4 nearest grid centers to (px,py), replicating the reference distance formula
// (sqrt(clip(aa+bb-2ab,1e-12))) with lower-index tie-break.  The 4 nearest
// lattice centers always lie inside a clamped 5x5 window around floor(p/8).
__device__ void top4cells(float px, float py, int* out) {
    int cx0 = (int)floorf(px * 0.125f);
    int cy0 = (int)floorf(py * 0.125f);
    int lx = min(max(cx0 - 2, 0), Wq - 5);
    int ly = min(max(cy0 - 2, 0), Hq - 5);
    float bd0 = 1e30f, bd1 = 1e30f, bd2 = 1e30f, bd3 = 1e30f;
    int   bi0 = -1, bi1 = -1, bi2 = -1, bi3 = -1;
    float aa = px*px + py*py;
    for (int yy = ly; yy < ly + 5; yy++) {
        float cy = (yy + 0.5f) * GS;
        for (int xx = lx; xx < lx + 5; xx++) {
            float cx = (xx + 0.5f) * GS;
            float bb = cx*cx + cy*cy;
            float ab = px*cx + py*cy;
            float d = sqrtf(fmaxf(aa + bb - 2.0f*ab, 1e-12f));
            int id = yy * Wq + xx;
            if (d < bd3) {
                if (d < bd2) {
                    bd3 = bd2; bi3 = bi2;
                    if (d < bd1) {
                        bd2 = bd1; bi2 = bi1;
                        if (d < bd0) { bd1 = bd0; bi1 = bi0; bd0 = d; bi0 = id; }
                        else         { bd1 = d; bi1 = id; }
                    } else { bd2 = d; bi2 = id; }
                } else { bd3 = d; bi3 = id; }
            }
        }
    }
    out[0] = bi0; out[1] = bi1; out[2] = bi2; out[3] = bi3;
}

// ---------------- K1a: per-cell inverse norms ----------------
__global__ void k_norms(const float* __restrict__ desc2) {
    int t = blockIdx.x * blockDim.x + threadIdx.x;
    if (t >= Bq*HWq) return;
    int b = t / HWq, m = t % HWq;
    const float* p = desc2 + (size_t)b*Cq*HWq + m;
    float ss = 0.f;
    #pragma unroll 8
    for (int c = 0; c < Cq; c++) { float v = p[(size_t)c*HWq]; ss += v*v; }
    g_inorm[t] = 1.0f / sqrtf(ss + 1e-8f);
}

// ---------------- K1b: transpose desc2 -> [b][m][c] (raw) ----------------
__global__ void k_transpose(const float* __restrict__ desc2) {
    __shared__ float tile[32][33];
    int b = blockIdx.z;
    int m0 = blockIdx.x * 32, c0 = blockIdx.y * 32;
    int tx = threadIdx.x, ty = threadIdx.y;   // 32 x 8
    #pragma unroll
    for (int q = 0; q < 4; q++) {
        int c = c0 + ty + q*8;
        tile[ty + q*8][tx] = desc2[((size_t)b*Cq + c)*HWq + m0 + tx];
    }
    __syncthreads();
    #pragma unroll
    for (int q = 0; q < 4; q++) {
        int m = m0 + ty + q*8;
        g_d2t[((size_t)b*HWq + m)*Cq + c0 + tx] = tile[tx][ty + q*8];
    }
}

// ---------------- K0: normalize kd + bilinear pos ----------------
__global__ void k_kd_pos(const float* __restrict__ kp1_desc,
                         const float* __restrict__ w_kp1) {
    __shared__ float red[256];
    int row = blockIdx.x;               // b*N + n
    int b = row / Nq;
    int c = threadIdx.x;

    float v = kp1_desc[(size_t)row*Cq + c];
    float ss = block_sum256(v*v, red);
    float kd = v / sqrtf(ss + 1e-8f);
    g_kd[(size_t)row*Cq + c] = kd;

    float x = w_kp1[row*2 + 0] * 0.125f - 0.5f;
    float y = w_kp1[row*2 + 1] * 0.125f - 0.5f;
    float fx = floorf(x), fy = floorf(y);
    float wx = x - fx, wy = y - fy;
    int x0 = min(max((int)fx, 0), Wq - 1);
    int x1 = min(x0 + 1, Wq - 1);
    int y0 = min(max((int)fy, 0), Hq - 1);
    int y1 = min(y0 + 1, Hq - 1);
    const float* D = g_d2t + (size_t)b*HWq*Cq;
    float d00 = D[(size_t)(y0*Wq + x0)*Cq + c];
    float d01 = D[(size_t)(y0*Wq + x1)*Cq + c];
    float d10 = D[(size_t)(y1*Wq + x0)*Cq + c];
    float d11 = D[(size_t)(y1*Wq + x1)*Cq + c];
    float top = d00*(1.f - wx) + d01*wx;
    float bot = d10*(1.f - wx) + d11*wx;
    float wv = top*(1.f - wy) + bot*wy;

    float ws = block_sum256(wv*wv, red);
    float wn = wv / sqrtf(ws + 1e-8f);
    float dot = block_sum256(kd*wn, red);
    if (c == 0) g_pos[row] = 2.0f - 2.0f*dot;
}

// ---------------- K2: neighbourhood cell ids (ids1 -> warp -> ids2) ---------
__global__ void k_nbr(const float* __restrict__ kp1,
                      const float* __restrict__ homo) {
    int t = blockIdx.x * blockDim.x + threadIdx.x;
    if (t >= Bq*Nq) return;
    int b = t / Nq;
    float px = kp1[t*2], py = kp1[t*2 + 1];
    const float* Hm = homo + b*9;
    int idx4[4];
    top4cells(px, py, idx4);
    #pragma unroll
    for (int q = 0; q < 4; q++) {
        int ci = idx4[q];
        int iy = ci / Wq, ix = ci % Wq;
        float cx = (ix + 0.5f)*GS, cy = (iy + 0.5f)*GS;
        float X = Hm[0]*cx + Hm[1]*cy + Hm[2];
        float Y = Hm[3]*cx + Hm[4]*cy + Hm[5];
        float Z = Hm[6]*cx + Hm[7]*cy + Hm[8];
        float wxp = X / (Z + 1e-8f);
        float wyp = Y / (Z + 1e-8f);
        top4cells(wxp, wyp, &g_nbr[(size_t)t*16 + q*4]);
    }
}

// ---------------- K3: fp32 GEMM  sim = 2 - 2*(kd @ d2t^T)*inorm ------------
#define TM 128
#define TN 128
#define TK 16
__global__ __launch_bounds__(256, 2) void k_gemm() {
    __shared__ float As[TK][TM + 4];
    __shared__ float Bs[TK][TN + 4];
    int bm = blockIdx.x, bn = blockIdx.y, b = blockIdx.z;
    int tid = threadIdx.x;
    int tx = tid & 15, ty = tid >> 4;
    int n0 = bn * TM, m0 = bm * TN;
    const float* A  = g_kd  + (size_t)b*Nq*Cq;
    const float* Bt = g_d2t + (size_t)b*HWq*Cq;

    float acc[8][8];
    #pragma unroll
    for (int i = 0; i < 8; i++)
        #pragma unroll
        for (int j = 0; j < 8; j++) acc[i][j] = 0.f;

    int lr = tid >> 2;            // 0..63
    int lk = (tid & 3) * 4;       // 0,4,8,12

    for (int k0 = 0; k0 < Cq; k0 += TK) {
        #pragma unroll
        for (int h = 0; h < 2; h++) {
            int row = lr + h*64;
            float4 va = *(const float4*)&A[(size_t)(n0 + row)*Cq + k0 + lk];
            As[lk+0][row] = va.x; As[lk+1][row] = va.y;
            As[lk+2][row] = va.z; As[lk+3][row] = va.w;
            int mrow = m0 + row;
            float4 vb = make_float4(0.f, 0.f, 0.f, 0.f);
            if (mrow < HWq) vb = *(const float4*)&Bt[(size_t)mrow*Cq + k0 + lk];
            Bs[lk+0][row] = vb.x; Bs[lk+1][row] = vb.y;
            Bs[lk+2][row] = vb.z; Bs[lk+3][row] = vb.w;
        }
        __syncthreads();
        #pragma unroll
        for (int kk = 0; kk < TK; kk++) {
            float af[8], bf[8];
            #pragma unroll
            for (int i = 0; i < 8; i++) af[i] = As[kk][ty*8 + i];
            #pragma unroll
            for (int j = 0; j < 8; j++) bf[j] = Bs[kk][tx*8 + j];
            #pragma unroll
            for (int i = 0; i < 8; i++)
                #pragma unroll
                for (int j = 0; j < 8; j++)
                    acc[i][j] = fmaf(af[i], bf[j], acc[i][j]);
        }
        __syncthreads();
    }

    float inorm[8];
    #pragma unroll
    for (int j = 0; j < 8; j++) {
        int m = m0 + tx*8 + j;
        inorm[j] = (m < HWq) ? g_inorm[b*HWq + m] : 0.f;
    }
    #pragma unroll
    for (int i = 0; i < 8; i++) {
        int n = n0 + ty*8 + i;
        float* out = g_sim + ((size_t)b*Nq + n)*HWq;
        int mbase = m0 + tx*8;
        if (mbase + 7 < HWq) {
            float4 o0, o1;
            o0.x = 2.f - 2.f*acc[i][0]*inorm[0];
            o0.y = 2.f - 2.f*acc[i][1]*inorm[1];
            o0.z = 2.f - 2.f*acc[i][2]*inorm[2];
            o0.w = 2.f - 2.f*acc[i][3]*inorm[3];
            o1.x = 2.f - 2.f*acc[i][4]*inorm[4];
            o1.y = 2.f - 2.f*acc[i][5]*inorm[5];
            o1.z = 2.f - 2.f*acc[i][6]*inorm[6];
            o1.w = 2.f - 2.f*acc[i][7]*inorm[7];
            *(float4*)&out[mbase]     = o0;
            *(float4*)&out[mbase + 4] = o1;
        } else {
            #pragma unroll
            for (int j = 0; j < 8; j++) {
                int m = mbase + j;
                if (m < HWq) out[m] = 2.f - 2.f*acc[i][j]*inorm[j];
            }
        }
    }
}

// ---------------- K3b: scatter +5 penalty per row ---------------------------
__global__ void k_penalty() {
    int t = blockIdx.x * blockDim.x + threadIdx.x;
    if (t >= Bq*Nq) return;
    float* row = g_sim + (size_t)t*HWq;
    #pragma unroll
    for (int q = 0; q < 16; q++) row[g_nbr[(size_t)t*16 + q]] += 5.0f;
}

// ---------------- K4: top-4 min per row + hinge -----------------------------
__global__ void k_top4() {
    __shared__ float sv[1024];
    __shared__ float rv[256];
    __shared__ int   ri[256];
    int row = blockIdx.x;
    int tid = threadIdx.x;
    const float* s = g_sim + (size_t)row*HWq;

    float b0 = 1e30f, b1 = 1e30f, b2 = 1e30f, b3 = 1e30f;
    for (int m = tid; m < HWq; m += 256) {
        float v = s[m];
        if (v < b3) {
            if (v < b2) {
                b3 = b2;
                if (v < b1) { b2 = b1; if (v < b0) { b1 = b0; b0 = v; } else b1 = v; }
                else b2 = v;
            } else b3 = v;
        }
    }
    sv[tid]       = b0;
    sv[tid + 256] = b1;
    sv[tid + 512] = b2;
    sv[tid + 768] = b3;
    __syncthreads();

    float pos = g_pos[row];
    float lsum = 0.f;
    for (int r = 0; r < 4; r++) {
        float mv = 1e30f; int mi = -1;
        for (int q = tid; q < 1024; q += 256) {
            float x = sv[q];
            if (x < mv) { mv = x; mi = q; }
        }
        rv[tid] = mv; ri[tid] = mi;
        __syncthreads();
        for (int st = 128; st > 0; st >>= 1) {
            if (tid < st && rv[tid + st] < rv[tid]) { rv[tid] = rv[tid + st]; ri[tid] = ri[tid + st]; }
            __syncthreads();
        }
        if (tid == 0) {
            lsum += fmaxf(pos - rv[0] + 1.0f, 0.f);
            sv[ri[0]] = 1e30f;
        }
        __syncthreads();
    }
    if (tid == 0) g_rowloss[row] = lsum;
}

// ---------------- K5: deterministic final mean ------------------------------
__global__ void k_final(float* out) {
    __shared__ float red[256];
    int tid = threadIdx.x;
    float acc = 0.f;
    for (int i = tid; i < Bq*Nq; i += 256) acc += g_rowloss[i];
    red[tid] = acc; __syncthreads();
    for (int s = 128; s > 0; s >>= 1) {
        if (tid < s) red[tid] += red[tid + s];
        __syncthreads();
    }
    if (tid == 0) out[0] = red[0] / (float)(Bq*Nq*NUM_NEG);
}

// ---------------- launch ----------------------------------------------------
extern "C" void kernel_launch(void* const* d_in, const int* in_sizes, int n_in,
                              void* d_out, int out_size) {
    const float* kp1      = (const float*)d_in[0];
    const float* w_kp1    = (const float*)d_in[1];
    const float* kp1_desc = (const float*)d_in[2];
    const float* desc2    = (const float*)d_in[3];
    const float* homo     = (const float*)d_in[4];
    float* out = (float*)d_out;

    k_norms<<<(Bq*HWq + 255)/256, 256>>>(desc2);
    k_transpose<<<dim3(HWq/32, Cq/32, Bq), dim3(32, 8)>>>(desc2);
    k_kd_pos<<<Bq*Nq, 256>>>(kp1_desc, w_kp1);
    k_nbr<<<(Bq*Nq + 255)/256, 256>>>(kp1, homo);
    k_gemm<<<dim3((HWq + TN - 1)/TN, Nq/TM, Bq), 256>>>();
    k_penalty<<<(Bq*Nq + 255)/256, 256>>>();
    k_top4<<<Bq*Nq, 256>>>();
    k_final<<<1, 256>>>(out);
}

// round 5
// speedup vs baseline: 1.3369x; 1.3369x over previous
#include <cuda_runtime.h>
#include <math.h>
#include <stdint.h>

#define Bq 4
#define Nq 1024
#define Cq 256
#define Hq 60
#define Wq 80
#define HWq (Hq*Wq)          // 4800
#define GS 8.0f
#define NUM_NEG 4

// ---------------- scratch (device globals; no allocs allowed) ----------------
__device__ float g_kd[Bq*Nq*Cq];            // normalized kp1 descriptors
__device__ float g_d2t[Bq*HWq*Cq];          // raw desc2 transposed [b][m][c]
__device__ float g_inorm[Bq*HWq];           // 1/sqrt(ss+eps) per cell
__device__ float g_pos[Bq*Nq];
__device__ int   g_nbr[Bq*Nq*16];           // 16 penalized cell ids per row
__device__ float g_sim[Bq*Nq*HWq];          // sim matrix (78.6 MB)
__device__ float g_rowloss[Bq*Nq];

// ---------------- helpers ----------------
__device__ __forceinline__ float block_sum256(float v, float* red) {
    int t = threadIdx.x;
    red[t] = v; __syncthreads();
    #pragma unroll
    for (int s = 128; s > 0; s >>= 1) {
        if (t < s) red[t] += red[t + s];
        __syncthreads();
    }
    float r = red[0]; __syncthreads();
    return r;
}

__device__ __forceinline__ uint32_t f2tf32(float x) {
    uint32_t u;
    asm("cvt.rna.tf32.f32 %0, %1;" : "=r"(u) : "f"(x));
    return u;
}

// 4 nearest grid centers to (px,py), replicating reference distance formula
// with lower-index tie-break.  Nearest 4 lattice centers always lie inside a
// clamped 5x5 window around floor(p/8).
__device__ void top4cells(float px, float py, int* out) {
    int cx0 = (int)floorf(px * 0.125f);
    int cy0 = (int)floorf(py * 0.125f);
    int lx = min(max(cx0 - 2, 0), Wq - 5);
    int ly = min(max(cy0 - 2, 0), Hq - 5);
    float bd0 = 1e30f, bd1 = 1e30f, bd2 = 1e30f, bd3 = 1e30f;
    int   bi0 = -1, bi1 = -1, bi2 = -1, bi3 = -1;
    float aa = px*px + py*py;
    for (int yy = ly; yy < ly + 5; yy++) {
        float cy = (yy + 0.5f) * GS;
        for (int xx = lx; xx < lx + 5; xx++) {
            float cx = (xx + 0.5f) * GS;
            float bb = cx*cx + cy*cy;
            float ab = px*cx + py*cy;
            float d = sqrtf(fmaxf(aa + bb - 2.0f*ab, 1e-12f));
            int id = yy * Wq + xx;
            if (d < bd3) {
                if (d < bd2) {
                    bd3 = bd2; bi3 = bi2;
                    if (d < bd1) {
                        bd2 = bd1; bi2 = bi1;
                        if (d < bd0) { bd1 = bd0; bi1 = bi0; bd0 = d; bi0 = id; }
                        else         { bd1 = d; bi1 = id; }
                    } else { bd2 = d; bi2 = id; }
                } else { bd3 = d; bi3 = id; }
            }
        }
    }
    out[0] = bi0; out[1] = bi1; out[2] = bi2; out[3] = bi3;
}

// ---------------- K1a: per-cell inverse norms ----------------
__global__ void k_norms(const float* __restrict__ desc2) {
    int t = blockIdx.x * blockDim.x + threadIdx.x;
    if (t >= Bq*HWq) return;
    int b = t / HWq, m = t % HWq;
    const float* p = desc2 + (size_t)b*Cq*HWq + m;
    float ss = 0.f;
    #pragma unroll 8
    for (int c = 0; c < Cq; c++) { float v = p[(size_t)c*HWq]; ss += v*v; }
    g_inorm[t] = 1.0f / sqrtf(ss + 1e-8f);
}

// ---------------- K1b: transpose desc2 -> [b][m][c] (raw) ----------------
__global__ void k_transpose(const float* __restrict__ desc2) {
    __shared__ float tile[32][33];
    int b = blockIdx.z;
    int m0 = blockIdx.x * 32, c0 = blockIdx.y * 32;
    int tx = threadIdx.x, ty = threadIdx.y;   // 32 x 8
    #pragma unroll
    for (int q = 0; q < 4; q++) {
        int c = c0 + ty + q*8;
        tile[ty + q*8][tx] = desc2[((size_t)b*Cq + c)*HWq + m0 + tx];
    }
    __syncthreads();
    #pragma unroll
    for (int q = 0; q < 4; q++) {
        int m = m0 + ty + q*8;
        g_d2t[((size_t)b*HWq + m)*Cq + c0 + tx] = tile[tx][ty + q*8];
    }
}

// ---------------- K0: normalize kd + bilinear pos ----------------
__global__ void k_kd_pos(const float* __restrict__ kp1_desc,
                         const float* __restrict__ w_kp1) {
    __shared__ float red[256];
    int row = blockIdx.x;               // b*N + n
    int b = row / Nq;
    int c = threadIdx.x;

    float v = kp1_desc[(size_t)row*Cq + c];
    float ss = block_sum256(v*v, red);
    float kd = v / sqrtf(ss + 1e-8f);
    g_kd[(size_t)row*Cq + c] = kd;

    float x = w_kp1[row*2 + 0] * 0.125f - 0.5f;
    float y = w_kp1[row*2 + 1] * 0.125f - 0.5f;
    float fx = floorf(x), fy = floorf(y);
    float wx = x - fx, wy = y - fy;
    int x0 = min(max((int)fx, 0), Wq - 1);
    int x1 = min(x0 + 1, Wq - 1);
    int y0 = min(max((int)fy, 0), Hq - 1);
    int y1 = min(y0 + 1, Hq - 1);
    const float* D = g_d2t + (size_t)b*HWq*Cq;
    float d00 = D[(size_t)(y0*Wq + x0)*Cq + c];
    float d01 = D[(size_t)(y0*Wq + x1)*Cq + c];
    float d10 = D[(size_t)(y1*Wq + x0)*Cq + c];
    float d11 = D[(size_t)(y1*Wq + x1)*Cq + c];
    float top = d00*(1.f - wx) + d01*wx;
    float bot = d10*(1.f - wx) + d11*wx;
    float wv = top*(1.f - wy) + bot*wy;

    float ws = block_sum256(wv*wv, red);
    float wn = wv / sqrtf(ws + 1e-8f);
    float dot = block_sum256(kd*wn, red);
    if (c == 0) g_pos[row] = 2.0f - 2.0f*dot;
}

// ---------------- K2: neighbourhood cell ids (one thread per (point, q)) ----
__global__ void k_nbr(const float* __restrict__ kp1,
                      const float* __restrict__ homo) {
    int idx = blockIdx.x * blockDim.x + threadIdx.x;
    if (idx >= Bq*Nq*4) return;
    int t = idx >> 2, q = idx & 3;
    int b = t / Nq;
    float px = kp1[t*2], py = kp1[t*2 + 1];
    const float* Hm = homo + b*9;
    int idx4[4];
    top4cells(px, py, idx4);
    int ci = idx4[q];
    int iy = ci / Wq, ix = ci % Wq;
    float cx = (ix + 0.5f)*GS, cy = (iy + 0.5f)*GS;
    float X = Hm[0]*cx + Hm[1]*cy + Hm[2];
    float Y = Hm[3]*cx + Hm[4]*cy + Hm[5];
    float Z = Hm[6]*cx + Hm[7]*cy + Hm[8];
    float wxp = X / (Z + 1e-8f);
    float wyp = Y / (Z + 1e-8f);
    top4cells(wxp, wyp, &g_nbr[(size_t)t*16 + q*4]);
}

// ---------------- K3: TF32 tensor-core GEMM  sim = 2 - 2*(kd @ d2t^T)*inorm -
// Block tile 128(n-rows) x 128(m-cols), K-chunk 32, 8 warps (2x4),
// warp tile 64x32 via mma.sync.m16n8k8 tf32.
__global__ __launch_bounds__(256) void k_gemm_tf32() {
    __shared__ uint32_t As[32][129];   // [k][row]  (stride 129: conflict-free stores)
    __shared__ uint32_t Bs[32][129];   // [k][col]
    int bm = blockIdx.x, bn = blockIdx.y, b = blockIdx.z;
    int tid = threadIdx.x;
    int lane = tid & 31, warp = tid >> 5;
    int wy = warp & 1, wx = warp >> 1;      // 2 x 4 warp grid
    int wrow = wy * 64, wcol = wx * 32;
    int g = lane >> 2, tig = lane & 3;
    int n0 = bn * 128, m0 = bm * 128;
    const float* A  = g_kd  + (size_t)b*Nq*Cq;
    const float* Bt = g_d2t + (size_t)b*HWq*Cq;

    float c[4][4][4];
    #pragma unroll
    for (int mt = 0; mt < 4; mt++)
        #pragma unroll
        for (int nt = 0; nt < 4; nt++)
            #pragma unroll
            for (int r = 0; r < 4; r++) c[mt][nt][r] = 0.f;

    int lrow = tid >> 3;     // 0..31
    int lkq  = tid & 7;      // 0..7 (float4 along k)

    for (int k0 = 0; k0 < Cq; k0 += 32) {
        #pragma unroll
        for (int h = 0; h < 4; h++) {
            int row = lrow + h*32;
            float4 va = *(const float4*)&A[(size_t)(n0 + row)*Cq + k0 + lkq*4];
            As[lkq*4+0][row] = f2tf32(va.x);
            As[lkq*4+1][row] = f2tf32(va.y);
            As[lkq*4+2][row] = f2tf32(va.z);
            As[lkq*4+3][row] = f2tf32(va.w);
            int mrow = m0 + row;
            float4 vb = make_float4(0.f,0.f,0.f,0.f);
            if (mrow < HWq) vb = *(const float4*)&Bt[(size_t)mrow*Cq + k0 + lkq*4];
            Bs[lkq*4+0][row] = f2tf32(vb.x);
            Bs[lkq*4+1][row] = f2tf32(vb.y);
            Bs[lkq*4+2][row] = f2tf32(vb.z);
            Bs[lkq*4+3][row] = f2tf32(vb.w);
        }
        __syncthreads();
        #pragma unroll
        for (int ks = 0; ks < 4; ks++) {
            int kk = ks * 8;
            uint32_t af[4][4], bf[4][2];
            #pragma unroll
            for (int mt = 0; mt < 4; mt++) {
                int rb = wrow + mt*16 + g;
                af[mt][0] = As[kk + tig    ][rb    ];
                af[mt][1] = As[kk + tig    ][rb + 8];
                af[mt][2] = As[kk + tig + 4][rb    ];
                af[mt][3] = As[kk + tig + 4][rb + 8];
            }
            #pragma unroll
            for (int nt = 0; nt < 4; nt++) {
                int cb = wcol + nt*8 + g;
                bf[nt][0] = Bs[kk + tig    ][cb];
                bf[nt][1] = Bs[kk + tig + 4][cb];
            }
            #pragma unroll
            for (int mt = 0; mt < 4; mt++)
                #pragma unroll
                for (int nt = 0; nt < 4; nt++) {
                    asm volatile(
                        "mma.sync.aligned.m16n8k8.row.col.f32.tf32.tf32.f32 "
                        "{%0,%1,%2,%3}, {%4,%5,%6,%7}, {%8,%9}, {%0,%1,%2,%3};"
                        : "+f"(c[mt][nt][0]), "+f"(c[mt][nt][1]),
                          "+f"(c[mt][nt][2]), "+f"(c[mt][nt][3])
                        : "r"(af[mt][0]), "r"(af[mt][1]), "r"(af[mt][2]), "r"(af[mt][3]),
                          "r"(bf[nt][0]), "r"(bf[nt][1]));
                }
        }
        __syncthreads();
    }

    // epilogue: sim = 2 - 2*acc*inorm[col]
    #pragma unroll
    for (int nt = 0; nt < 4; nt++) {
        int col = m0 + wcol + nt*8 + tig*2;
        if (col >= HWq) continue;
        float in0 = g_inorm[b*HWq + col];
        float in1 = g_inorm[b*HWq + col + 1];
        #pragma unroll
        for (int mt = 0; mt < 4; mt++) {
            int r0 = n0 + wrow + mt*16 + g;
            float2 o0, o1;
            o0.x = 2.f - 2.f*c[mt][nt][0]*in0;
            o0.y = 2.f - 2.f*c[mt][nt][1]*in1;
            o1.x = 2.f - 2.f*c[mt][nt][2]*in0;
            o1.y = 2.f - 2.f*c[mt][nt][3]*in1;
            *(float2*)&g_sim[((size_t)b*Nq + r0    )*HWq + col] = o0;
            *(float2*)&g_sim[((size_t)b*Nq + r0 + 8)*HWq + col] = o1;
        }
    }
}

// ---------------- K4: top-4 min per row (excluding nbr cells) + hinge -------
// Penalized cells (sim+5k, k>=1) are always >= 5 > 4 >= any unpenalized sim,
// so excluding them from the scan is exactly equivalent to the reference.
__global__ void k_top4() {
    __shared__ float sv[1024];
    __shared__ float rv[256];
    __shared__ int   ri[256];
    __shared__ int   nb[16];
    int row = blockIdx.x;
    int tid = threadIdx.x;
    const float* s = g_sim + (size_t)row*HWq;

    if (tid < 16) nb[tid] = g_nbr[(size_t)row*16 + tid];
    __syncthreads();

    float b0 = 1e30f, b1 = 1e30f, b2 = 1e30f, b3 = 1e30f;
    for (int m = tid; m < HWq; m += 256) {
        float v = s[m];
        if (v < b3) {
            bool skip = false;
            #pragma unroll
            for (int q = 0; q < 16; q++) skip |= (m == nb[q]);
            if (skip) continue;
            if (v < b2) {
                b3 = b2;
                if (v < b1) { b2 = b1; if (v < b0) { b1 = b0; b0 = v; } else b1 = v; }
                else b2 = v;
            } else b3 = v;
        }
    }
    sv[tid]       = b0;
    sv[tid + 256] = b1;
    sv[tid + 512] = b2;
    sv[tid + 768] = b3;
    __syncthreads();

    float pos = g_pos[row];
    float lsum = 0.f;
    for (int r = 0; r < 4; r++) {
        float mv = 1e30f; int mi = -1;
        for (int q = tid; q < 1024; q += 256) {
            float x = sv[q];
            if (x < mv) { mv = x; mi = q; }
        }
        rv[tid] = mv; ri[tid] = mi;
        __syncthreads();
        for (int st = 128; st > 0; st >>= 1) {
            if (tid < st && rv[tid + st] < rv[tid]) { rv[tid] = rv[tid + st]; ri[tid] = ri[tid + st]; }
            __syncthreads();
        }
        if (tid == 0) {
            lsum += fmaxf(pos - rv[0] + 1.0f, 0.f);
            sv[ri[0]] = 1e30f;
        }
        __syncthreads();
    }
    if (tid == 0) g_rowloss[row] = lsum;
}

// ---------------- K5: deterministic final mean ------------------------------
__global__ void k_final(float* out) {
    __shared__ float red[256];
    int tid = threadIdx.x;
    float acc = 0.f;
    for (int i = tid; i < Bq*Nq; i += 256) acc += g_rowloss[i];
    red[tid] = acc; __syncthreads();
    for (int s = 128; s > 0; s >>= 1) {
        if (tid < s) red[tid] += red[tid + s];
        __syncthreads();
    }
    if (tid == 0) out[0] = red[0] / (float)(Bq*Nq*NUM_NEG);
}

// ---------------- launch ----------------------------------------------------
extern "C" void kernel_launch(void* const* d_in, const int* in_sizes, int n_in,
                              void* d_out, int out_size) {
    const float* kp1      = (const float*)d_in[0];
    const float* w_kp1    = (const float*)d_in[1];
    const float* kp1_desc = (const float*)d_in[2];
    const float* desc2    = (const float*)d_in[3];
    const float* homo     = (const float*)d_in[4];
    float* out = (float*)d_out;

    k_norms<<<(Bq*HWq + 255)/256, 256>>>(desc2);
    k_transpose<<<dim3(HWq/32, Cq/32, Bq), dim3(32, 8)>>>(desc2);
    k_kd_pos<<<Bq*Nq, 256>>>(kp1_desc, w_kp1);
    k_nbr<<<(Bq*Nq*4 + 127)/128, 128>>>(kp1, homo);
    k_gemm_tf32<<<dim3((HWq + 127)/128, Nq/128, Bq), 256>>>();
    k_top4<<<Bq*Nq, 256>>>();
    k_final<<<1, 256>>>(out);
}

// round 6
// speedup vs baseline: 1.6538x; 1.2370x over previous
#include <cuda_runtime.h>
#include <math.h>
#include <stdint.h>

#define Bq 4
#define Nq 1024
#define Cq 256
#define Hq 60
#define Wq 80
#define HWq (Hq*Wq)          // 4800
#define GS 8.0f
#define NUM_NEG 4
#define NSPLIT 38            // ceil(4800/128) col splits

// ---------------- scratch (device globals; no allocs allowed) ----------------
__device__ float g_kd[Bq*Nq*Cq];            // normalized kp1 descriptors
__device__ float g_d2t[Bq*HWq*Cq];          // raw desc2 transposed [b][m][c]
__device__ float g_inorm[Bq*HWq];           // 1/sqrt(ss+eps) per cell
__device__ float g_pos[Bq*Nq];
__device__ int   g_nbr[Bq*Nq*16];           // 16 penalized cell ids per row
__device__ float g_part[Bq*Nq*NSPLIT*4];    // per-split partial top-4 (2.5 MB)
__device__ float g_rowloss[Bq*Nq];

// ---------------- helpers ----------------
__device__ __forceinline__ float block_sum256(float v, float* red) {
    int t = threadIdx.x;
    red[t] = v; __syncthreads();
    #pragma unroll
    for (int s = 128; s > 0; s >>= 1) {
        if (t < s) red[t] += red[t + s];
        __syncthreads();
    }
    float r = red[0]; __syncthreads();
    return r;
}

__device__ __forceinline__ uint32_t f2tf32(float x) {
    uint32_t u;
    asm("cvt.rna.tf32.f32 %0, %1;" : "=r"(u) : "f"(x));
    return u;
}

__device__ __forceinline__ void ins4(float* t, float v) {
    if (v < t[3]) {
        if (v < t[2]) {
            t[3] = t[2];
            if (v < t[1]) { t[2] = t[1]; if (v < t[0]) { t[1] = t[0]; t[0] = v; } else t[1] = v; }
            else t[2] = v;
        } else t[3] = v;
    }
}

// 4 nearest grid centers to (px,py), replicating reference distance formula
// with lower-index tie-break.  Nearest 4 lattice centers always lie inside a
// clamped 5x5 window around floor(p/8).
__device__ void top4cells(float px, float py, int* out) {
    int cx0 = (int)floorf(px * 0.125f);
    int cy0 = (int)floorf(py * 0.125f);
    int lx = min(max(cx0 - 2, 0), Wq - 5);
    int ly = min(max(cy0 - 2, 0), Hq - 5);
    float bd0 = 1e30f, bd1 = 1e30f, bd2 = 1e30f, bd3 = 1e30f;
    int   bi0 = -1, bi1 = -1, bi2 = -1, bi3 = -1;
    float aa = px*px + py*py;
    for (int yy = ly; yy < ly + 5; yy++) {
        float cy = (yy + 0.5f) * GS;
        for (int xx = lx; xx < lx + 5; xx++) {
            float cx = (xx + 0.5f) * GS;
            float bb = cx*cx + cy*cy;
            float ab = px*cx + py*cy;
            float d = sqrtf(fmaxf(aa + bb - 2.0f*ab, 1e-12f));
            int id = yy * Wq + xx;
            if (d < bd3) {
                if (d < bd2) {
                    bd3 = bd2; bi3 = bi2;
                    if (d < bd1) {
                        bd2 = bd1; bi2 = bi1;
                        if (d < bd0) { bd1 = bd0; bi1 = bi0; bd0 = d; bi0 = id; }
                        else         { bd1 = d; bi1 = id; }
                    } else { bd2 = d; bi2 = id; }
                } else { bd3 = d; bi3 = id; }
            }
        }
    }
    out[0] = bi0; out[1] = bi1; out[2] = bi2; out[3] = bi3;
}

// ---------------- K1a: per-cell inverse norms ----------------
__global__ void k_norms(const float* __restrict__ desc2) {
    int t = blockIdx.x * blockDim.x + threadIdx.x;
    if (t >= Bq*HWq) return;
    int b = t / HWq, m = t % HWq;
    const float* p = desc2 + (size_t)b*Cq*HWq + m;
    float ss = 0.f;
    #pragma unroll 8
    for (int c = 0; c < Cq; c++) { float v = p[(size_t)c*HWq]; ss += v*v; }
    g_inorm[t] = 1.0f / sqrtf(ss + 1e-8f);
}

// ---------------- K1b: transpose desc2 -> [b][m][c] (raw) ----------------
__global__ void k_transpose(const float* __restrict__ desc2) {
    __shared__ float tile[32][33];
    int b = blockIdx.z;
    int m0 = blockIdx.x * 32, c0 = blockIdx.y * 32;
    int tx = threadIdx.x, ty = threadIdx.y;   // 32 x 8
    #pragma unroll
    for (int q = 0; q < 4; q++) {
        int c = c0 + ty + q*8;
        tile[ty + q*8][tx] = desc2[((size_t)b*Cq + c)*HWq + m0 + tx];
    }
    __syncthreads();
    #pragma unroll
    for (int q = 0; q < 4; q++) {
        int m = m0 + ty + q*8;
        g_d2t[((size_t)b*HWq + m)*Cq + c0 + tx] = tile[tx][ty + q*8];
    }
}

// ---------------- K0: normalize kd + bilinear pos ----------------
__global__ void k_kd_pos(const float* __restrict__ kp1_desc,
                         const float* __restrict__ w_kp1) {
    __shared__ float red[256];
    int row = blockIdx.x;               // b*N + n
    int b = row / Nq;
    int c = threadIdx.x;

    float v = kp1_desc[(size_t)row*Cq + c];
    float ss = block_sum256(v*v, red);
    float kd = v / sqrtf(ss + 1e-8f);
    g_kd[(size_t)row*Cq + c] = kd;

    float x = w_kp1[row*2 + 0] * 0.125f - 0.5f;
    float y = w_kp1[row*2 + 1] * 0.125f - 0.5f;
    float fx = floorf(x), fy = floorf(y);
    float wx = x - fx, wy = y - fy;
    int x0 = min(max((int)fx, 0), Wq - 1);
    int x1 = min(x0 + 1, Wq - 1);
    int y0 = min(max((int)fy, 0), Hq - 1);
    int y1 = min(y0 + 1, Hq - 1);
    const float* D = g_d2t + (size_t)b*HWq*Cq;
    float d00 = D[(size_t)(y0*Wq + x0)*Cq + c];
    float d01 = D[(size_t)(y0*Wq + x1)*Cq + c];
    float d10 = D[(size_t)(y1*Wq + x0)*Cq + c];
    float d11 = D[(size_t)(y1*Wq + x1)*Cq + c];
    float top = d00*(1.f - wx) + d01*wx;
    float bot = d10*(1.f - wx) + d11*wx;
    float wv = top*(1.f - wy) + bot*wy;

    float ws = block_sum256(wv*wv, red);
    float wn = wv / sqrtf(ws + 1e-8f);
    float dot = block_sum256(kd*wn, red);
    if (c == 0) g_pos[row] = 2.0f - 2.0f*dot;
}

// ---------------- K2: neighbourhood cell ids (one thread per (point, q)) ----
__global__ void k_nbr(const float* __restrict__ kp1,
                      const float* __restrict__ homo) {
    int idx = blockIdx.x * blockDim.x + threadIdx.x;
    if (idx >= Bq*Nq*4) return;
    int t = idx >> 2, q = idx & 3;
    int b = t / Nq;
    float px = kp1[t*2], py = kp1[t*2 + 1];
    const float* Hm = homo + b*9;
    int idx4[4];
    top4cells(px, py, idx4);
    int ci = idx4[q];
    int iy = ci / Wq, ix = ci % Wq;
    float cx = (ix + 0.5f)*GS, cy = (iy + 0.5f)*GS;
    float X = Hm[0]*cx + Hm[1]*cy + Hm[2];
    float Y = Hm[3]*cx + Hm[4]*cy + Hm[5];
    float Z = Hm[6]*cx + Hm[7]*cy + Hm[8];
    float wxp = X / (Z + 1e-8f);
    float wyp = Y / (Z + 1e-8f);
    top4cells(wxp, wyp, &g_nbr[(size_t)t*16 + q*4]);
}

// ---------------- K3: TF32 GEMM + fused per-split top-4 ---------------------
// Block: 128 rows x 128 cols, 8 warps (2x4), warp tile 64x32, m16n8k8 tf32.
// Epilogue keeps a per-thread running min-4 per row (excluding penalized
// cells via bitmask), reduces per-row across the block, writes 4 floats/row.
__global__ __launch_bounds__(256) void k_gemm_top4() {
    __shared__ union {
        struct { uint32_t A[32][129]; uint32_t B[32][129]; } ld;
        float red[128][64];
    } sm;
    __shared__ uint32_t mask[128][4];   // per-row, per-local-col penalty bits

    int bm = blockIdx.x, bn = blockIdx.y, b = blockIdx.z;
    int tid = threadIdx.x;
    int lane = tid & 31, warp = tid >> 5;
    int wy = warp & 1, wx = warp >> 1;      // 2 x 4 warp grid
    int wrow = wy * 64, wcol = wx * 32;
    int g = lane >> 2, tig = lane & 3;
    int n0 = bn * 128, m0 = bm * 128;
    const float* A  = g_kd  + (size_t)b*Nq*Cq;
    const float* Bt = g_d2t + (size_t)b*HWq*Cq;

    // build penalty bitmask for this block's 128 rows x 128 cols
    if (tid < 128) { mask[tid][0] = 0; mask[tid][1] = 0; mask[tid][2] = 0; mask[tid][3] = 0; }
    __syncthreads();
    {
        int row = tid >> 1;                 // 0..127
        int qb  = (tid & 1) * 8;
        const int* nb = &g_nbr[(size_t)(b*Nq + n0 + row)*16];
        #pragma unroll
        for (int q = 0; q < 8; q++) {
            int id = nb[qb + q];
            int loc = id - m0;
            if (loc >= 0 && loc < 128)
                atomicOr(&mask[row][loc >> 5], 1u << (loc & 31));
        }
    }

    float c[4][4][4];
    #pragma unroll
    for (int mt = 0; mt < 4; mt++)
        #pragma unroll
        for (int nt = 0; nt < 4; nt++)
            #pragma unroll
            for (int r = 0; r < 4; r++) c[mt][nt][r] = 0.f;

    int lrow = tid >> 3;     // 0..31
    int lkq  = tid & 7;      // 0..7 (float4 along k)

    __syncthreads();
    for (int k0 = 0; k0 < Cq; k0 += 32) {
        #pragma unroll
        for (int h = 0; h < 4; h++) {
            int row = lrow + h*32;
            float4 va = *(const float4*)&A[(size_t)(n0 + row)*Cq + k0 + lkq*4];
            sm.ld.A[lkq*4+0][row] = f2tf32(va.x);
            sm.ld.A[lkq*4+1][row] = f2tf32(va.y);
            sm.ld.A[lkq*4+2][row] = f2tf32(va.z);
            sm.ld.A[lkq*4+3][row] = f2tf32(va.w);
            int mrow = m0 + row;
            float4 vb = make_float4(0.f,0.f,0.f,0.f);
            if (mrow < HWq) vb = *(const float4*)&Bt[(size_t)mrow*Cq + k0 + lkq*4];
            sm.ld.B[lkq*4+0][row] = f2tf32(vb.x);
            sm.ld.B[lkq*4+1][row] = f2tf32(vb.y);
            sm.ld.B[lkq*4+2][row] = f2tf32(vb.z);
            sm.ld.B[lkq*4+3][row] = f2tf32(vb.w);
        }
        __syncthreads();
        #pragma unroll
        for (int ks = 0; ks < 4; ks++) {
            int kk = ks * 8;
            uint32_t af[4][4], bf[4][2];
            #pragma unroll
            for (int mt = 0; mt < 4; mt++) {
                int rb = wrow + mt*16 + g;
                af[mt][0] = sm.ld.A[kk + tig    ][rb    ];
                af[mt][1] = sm.ld.A[kk + tig    ][rb + 8];
                af[mt][2] = sm.ld.A[kk + tig + 4][rb    ];
                af[mt][3] = sm.ld.A[kk + tig + 4][rb + 8];
            }
            #pragma unroll
            for (int nt = 0; nt < 4; nt++) {
                int cb = wcol + nt*8 + g;
                bf[nt][0] = sm.ld.B[kk + tig    ][cb];
                bf[nt][1] = sm.ld.B[kk + tig + 4][cb];
            }
            #pragma unroll
            for (int mt = 0; mt < 4; mt++)
                #pragma unroll
                for (int nt = 0; nt < 4; nt++) {
                    asm volatile(
                        "mma.sync.aligned.m16n8k8.row.col.f32.tf32.tf32.f32 "
                        "{%0,%1,%2,%3}, {%4,%5,%6,%7}, {%8,%9}, {%0,%1,%2,%3};"
                        : "+f"(c[mt][nt][0]), "+f"(c[mt][nt][1]),
                          "+f"(c[mt][nt][2]), "+f"(c[mt][nt][3])
                        : "r"(af[mt][0]), "r"(af[mt][1]), "r"(af[mt][2]), "r"(af[mt][3]),
                          "r"(bf[nt][0]), "r"(bf[nt][1]));
                }
        }
        __syncthreads();
    }

    // ---- epilogue: per-thread running top-4 per row ----
    float t4[8][4];
    #pragma unroll
    for (int r = 0; r < 8; r++)
        #pragma unroll
        for (int s = 0; s < 4; s++) t4[r][s] = 1e30f;

    #pragma unroll
    for (int nt = 0; nt < 4; nt++) {
        int coll = wcol + nt*8 + tig*2;       // local col (even)
        int colg = m0 + coll;
        bool ok0 = colg < HWq, ok1 = (colg + 1) < HWq;
        float in0 = ok0 ? g_inorm[b*HWq + colg]     : 0.f;
        float in1 = ok1 ? g_inorm[b*HWq + colg + 1] : 0.f;
        #pragma unroll
        for (int mt = 0; mt < 4; mt++) {
            int lr0 = wrow + mt*16 + g;
            int lr1 = lr0 + 8;
            float v00 = 2.f - 2.f*c[mt][nt][0]*in0;
            float v01 = 2.f - 2.f*c[mt][nt][1]*in1;
            float v10 = 2.f - 2.f*c[mt][nt][2]*in0;
            float v11 = 2.f - 2.f*c[mt][nt][3]*in1;
            uint32_t m0b0 = mask[lr0][coll >> 5], m0b1 = mask[lr0][(coll+1) >> 5];
            uint32_t m1b0 = mask[lr1][coll >> 5], m1b1 = mask[lr1][(coll+1) >> 5];
            if (ok0 && !((m0b0 >> (coll & 31)) & 1))       ins4(t4[mt*2],     v00);
            if (ok1 && !((m0b1 >> ((coll+1) & 31)) & 1))   ins4(t4[mt*2],     v01);
            if (ok0 && !((m1b0 >> (coll & 31)) & 1))       ins4(t4[mt*2 + 1], v10);
            if (ok1 && !((m1b1 >> ((coll+1) & 31)) & 1))   ins4(t4[mt*2 + 1], v11);
        }
    }

    // ---- block reduction: 16 threads x 4 candidates -> top-4 per row ----
    __syncthreads();   // ld union dead, red live
    #pragma unroll
    for (int mt = 0; mt < 4; mt++) {
        int lr0 = wrow + mt*16 + g;
        int slot = (wx*4 + tig) * 4;
        *(float4*)&sm.red[lr0    ][slot] = *(float4*)t4[mt*2];
        *(float4*)&sm.red[lr0 + 8][slot] = *(float4*)t4[mt*2 + 1];
    }
    __syncthreads();
    if (tid < 128) {
        float tt[4] = {1e30f, 1e30f, 1e30f, 1e30f};
        const float* r = sm.red[tid];
        #pragma unroll 8
        for (int q = 0; q < 64; q++) ins4(tt, r[q]);
        float4 o = make_float4(tt[0], tt[1], tt[2], tt[3]);
        *(float4*)&g_part[((size_t)(b*Nq + n0 + tid)*NSPLIT + bm)*4] = o;
    }
}

// ---------------- K4: merge per-split partials, hinge ----------------------
// one warp per row; merge 38*4 = 152 candidate values
__global__ void k_merge() {
    int row = blockIdx.x * 4 + (threadIdx.x >> 5);   // 4 warps/block
    int lane = threadIdx.x & 31;
    const float* p = &g_part[(size_t)row*NSPLIT*4];
    float t[4] = {1e30f, 1e30f, 1e30f, 1e30f};
    for (int i = lane; i < NSPLIT*4; i += 32) ins4(t, p[i]);
    // warp merge of sorted quads
    #pragma unroll
    for (int off = 16; off > 0; off >>= 1) {
        float o0 = __shfl_xor_sync(0xffffffffu, t[0], off);
        float o1 = __shfl_xor_sync(0xffffffffu, t[1], off);
        float o2 = __shfl_xor_sync(0xffffffffu, t[2], off);
        float o3 = __shfl_xor_sync(0xffffffffu, t[3], off);
        float a[4] = {t[0], t[1], t[2], t[3]};
        float o[4] = {o0, o1, o2, o3};
        int ia = 0, ib = 0;
        #pragma unroll
        for (int k = 0; k < 4; k++) {
            float av = (ia < 4) ? a[ia] : 1e30f;
            float bv = (ib < 4) ? o[ib] : 1e30f;
            if (av <= bv) { t[k] = av; ia++; } else { t[k] = bv; ib++; }
        }
    }
    if (lane == 0) {
        float pos = g_pos[row];
        float lsum = 0.f;
        #pragma unroll
        for (int r = 0; r < 4; r++) lsum += fmaxf(pos - t[r] + 1.0f, 0.f);
        g_rowloss[row] = lsum;
    }
}

// ---------------- K5: deterministic final mean ------------------------------
__global__ void k_final(float* out) {
    __shared__ float red[256];
    int tid = threadIdx.x;
    float acc = 0.f;
    for (int i = tid; i < Bq*Nq; i += 256) acc += g_rowloss[i];
    red[tid] = acc; __syncthreads();
    for (int s = 128; s > 0; s >>= 1) {
        if (tid < s) red[tid] += red[tid + s];
        __syncthreads();
    }
    if (tid == 0) out[0] = red[0] / (float)(Bq*Nq*NUM_NEG);
}

// ---------------- launch ----------------------------------------------------
extern "C" void kernel_launch(void* const* d_in, const int* in_sizes, int n_in,
                              void* d_out, int out_size) {
    const float* kp1      = (const float*)d_in[0];
    const float* w_kp1    = (const float*)d_in[1];
    const float* kp1_desc = (const float*)d_in[2];
    const float* desc2    = (const float*)d_in[3];
    const float* homo     = (const float*)d_in[4];
    float* out = (float*)d_out;

    k_norms<<<(Bq*HWq + 255)/256, 256>>>(desc2);
    k_transpose<<<dim3(HWq/32, Cq/32, Bq), dim3(32, 8)>>>(desc2);
    k_kd_pos<<<Bq*Nq, 256>>>(kp1_desc, w_kp1);
    k_nbr<<<(Bq*Nq*4 + 127)/128, 128>>>(kp1, homo);
    k_gemm_top4<<<dim3(NSPLIT, Nq/128, Bq), 256>>>();
    k_merge<<<Bq*Nq/4, 128>>>();
    k_final<<<1, 256>>>(out);
}

// round 8
// speedup vs baseline: 2.8256x; 1.7086x over previous
#include <cuda_runtime.h>
#include <cuda_bf16.h>
#include <math.h>
#include <stdint.h>

#define Bq 4
#define Nq 1024
#define Cq 256
#define Hq 60
#define Wq 80
#define HWq (Hq*Wq)          // 4800
#define GS 8.0f
#define NUM_NEG 4
#define NSPLIT 38            // ceil(4800/128) col splits
#define MPAD (NSPLIT*128)    // 4864 padded cols
#define RSTRIDE 72           // smem row stride in bf16 elems (144 B = 36 words)

// ---------------- scratch (device globals; no allocs allowed) ----------------
__device__ float g_d2t[Bq*HWq*Cq];            // raw desc2 transposed [b][m][c]
__device__ float g_inorm[Bq*HWq];             // 1/sqrt(ss+eps) per cell
__device__ __nv_bfloat16 g_kdb[Bq*Nq*Cq];     // normalized kp1 desc, bf16
__device__ __nv_bfloat16 g_d2b[Bq*MPAD*Cq];   // normalized desc2, bf16, padded
__device__ float g_pos[Bq*Nq];
__device__ int   g_nbr[Bq*Nq*16];             // 16 penalized cell ids per row
__device__ float g_part[Bq*Nq*NSPLIT*4];      // per-split partial top-4
__device__ float g_rowloss[Bq*Nq];

// ---------------- helpers ----------------
__device__ __forceinline__ float block_sum256(float v, float* red) {
    int t = threadIdx.x;
    red[t] = v; __syncthreads();
    #pragma unroll
    for (int s = 128; s > 0; s >>= 1) {
        if (t < s) red[t] += red[t + s];
        __syncthreads();
    }
    float r = red[0]; __syncthreads();
    return r;
}

__device__ __forceinline__ void ins4(float* t, float v) {
    if (v < t[3]) {
        if (v < t[2]) {
            t[3] = t[2];
            if (v < t[1]) { t[2] = t[1]; if (v < t[0]) { t[1] = t[0]; t[0] = v; } else t[1] = v; }
            else t[2] = v;
        } else t[3] = v;
    }
}

// 4 nearest grid centers to (px,py), replicating reference distance formula
// with lower-index tie-break.  Nearest 4 lattice centers always lie inside a
// clamped 5x5 window around floor(p/8).
__device__ void top4cells(float px, float py, int* out) {
    int cx0 = (int)floorf(px * 0.125f);
    int cy0 = (int)floorf(py * 0.125f);
    int lx = min(max(cx0 - 2, 0), Wq - 5);
    int ly = min(max(cy0 - 2, 0), Hq - 5);
    float bd0 = 1e30f, bd1 = 1e30f, bd2 = 1e30f, bd3 = 1e30f;
    int   bi0 = -1, bi1 = -1, bi2 = -1, bi3 = -1;
    float aa = px*px + py*py;
    for (int yy = ly; yy < ly + 5; yy++) {
        float cy = (yy + 0.5f) * GS;
        for (int xx = lx; xx < lx + 5; xx++) {
            float cx = (xx + 0.5f) * GS;
            float bb = cx*cx + cy*cy;
            float ab = px*cx + py*cy;
            float d = sqrtf(fmaxf(aa + bb - 2.0f*ab, 1e-12f));
            int id = yy * Wq + xx;
            if (d < bd3) {
                if (d < bd2) {
                    bd3 = bd2; bi3 = bi2;
                    if (d < bd1) {
                        bd2 = bd1; bi2 = bi1;
                        if (d < bd0) { bd1 = bd0; bi1 = bi0; bd0 = d; bi0 = id; }
                        else         { bd1 = d; bi1 = id; }
                    } else { bd2 = d; bi2 = id; }
                } else { bd3 = d; bi3 = id; }
            }
        }
    }
    out[0] = bi0; out[1] = bi1; out[2] = bi2; out[3] = bi3;
}

// ---------------- K1a: per-cell inverse norms ----------------
__global__ void k_norms(const float* __restrict__ desc2) {
    int t = blockIdx.x * blockDim.x + threadIdx.x;
    if (t >= Bq*HWq) return;
    int b = t / HWq, m = t % HWq;
    const float* p = desc2 + (size_t)b*Cq*HWq + m;
    float ss = 0.f;
    #pragma unroll 8
    for (int c = 0; c < Cq; c++) { float v = p[(size_t)c*HWq]; ss += v*v; }
    g_inorm[t] = 1.0f / sqrtf(ss + 1e-8f);
}

// ---------------- K1b: transpose desc2 -> [b][m][c] (raw, fp32) -------------
__global__ void k_transpose(const float* __restrict__ desc2) {
    __shared__ float tile[32][33];
    int b = blockIdx.z;
    int m0 = blockIdx.x * 32, c0 = blockIdx.y * 32;
    int tx = threadIdx.x, ty = threadIdx.y;   // 32 x 8
    #pragma unroll
    for (int q = 0; q < 4; q++) {
        int c = c0 + ty + q*8;
        tile[ty + q*8][tx] = desc2[((size_t)b*Cq + c)*HWq + m0 + tx];
    }
    __syncthreads();
    #pragma unroll
    for (int q = 0; q < 4; q++) {
        int m = m0 + ty + q*8;
        g_d2t[((size_t)b*HWq + m)*Cq + c0 + tx] = tile[tx][ty + q*8];
    }
}

// ---------------- K1c: normalized bf16 desc2, padded to MPAD rows -----------
__global__ void k_d2b() {
    int t = blockIdx.x * blockDim.x + threadIdx.x;
    if (t >= Bq*MPAD*Cq/4) return;
    int e = t * 4;
    int b = e / (MPAD*Cq);
    int rem = e % (MPAD*Cq);
    int m = rem / Cq;
    int c = rem % Cq;
    __nv_bfloat16 o[4];
    if (m < HWq) {
        float inr = g_inorm[b*HWq + m];
        float4 v = *(const float4*)&g_d2t[((size_t)b*HWq + m)*Cq + c];
        o[0] = __float2bfloat16(v.x*inr); o[1] = __float2bfloat16(v.y*inr);
        o[2] = __float2bfloat16(v.z*inr); o[3] = __float2bfloat16(v.w*inr);
    } else {
        o[0] = o[1] = o[2] = o[3] = __float2bfloat16(0.f);
    }
    *(uint2*)&g_d2b[(size_t)b*MPAD*Cq + (size_t)m*Cq + c] = *(uint2*)o;
}

// ---------------- K0: normalize kd (store bf16) + bilinear pos (fp32) -------
__global__ void k_kd_pos(const float* __restrict__ kp1_desc,
                         const float* __restrict__ w_kp1) {
    __shared__ float red[256];
    int row = blockIdx.x;               // b*N + n
    int b = row / Nq;
    int c = threadIdx.x;

    float v = kp1_desc[(size_t)row*Cq + c];
    float ss = block_sum256(v*v, red);
    float kd = v / sqrtf(ss + 1e-8f);
    g_kdb[(size_t)row*Cq + c] = __float2bfloat16(kd);

    float x = w_kp1[row*2 + 0] * 0.125f - 0.5f;
    float y = w_kp1[row*2 + 1] * 0.125f - 0.5f;
    float fx = floorf(x), fy = floorf(y);
    float wx = x - fx, wy = y - fy;
    int x0 = min(max((int)fx, 0), Wq - 1);
    int x1 = min(x0 + 1, Wq - 1);
    int y0 = min(max((int)fy, 0), Hq - 1);
    int y1 = min(y0 + 1, Hq - 1);
    const float* D = g_d2t + (size_t)b*HWq*Cq;
    float d00 = D[(size_t)(y0*Wq + x0)*Cq + c];
    float d01 = D[(size_t)(y0*Wq + x1)*Cq + c];
    float d10 = D[(size_t)(y1*Wq + x0)*Cq + c];
    float d11 = D[(size_t)(y1*Wq + x1)*Cq + c];
    float top = d00*(1.f - wx) + d01*wx;
    float bot = d10*(1.f - wx) + d11*wx;
    float wv = top*(1.f - wy) + bot*wy;

    float ws = block_sum256(wv*wv, red);
    float wn = wv / sqrtf(ws + 1e-8f);
    float dot = block_sum256(kd*wn, red);
    if (c == 0) g_pos[row] = 2.0f - 2.0f*dot;
}

// ---------------- K2: neighbourhood cell ids (one thread per (point, q)) ----
__global__ void k_nbr(const float* __restrict__ kp1,
                      const float* __restrict__ homo) {
    int idx = blockIdx.x * blockDim.x + threadIdx.x;
    if (idx >= Bq*Nq*4) return;
    int t = idx >> 2, q = idx & 3;
    int b = t / Nq;
    float px = kp1[t*2], py = kp1[t*2 + 1];
    const float* Hm = homo + b*9;
    int idx4[4];
    top4cells(px, py, idx4);
    int ci = idx4[q];
    int iy = ci / Wq, ix = ci % Wq;
    float cx = (ix + 0.5f)*GS, cy = (iy + 0.5f)*GS;
    float X = Hm[0]*cx + Hm[1]*cy + Hm[2];
    float Y = Hm[3]*cx + Hm[4]*cy + Hm[5];
    float Z = Hm[6]*cx + Hm[7]*cy + Hm[8];
    float wxp = X / (Z + 1e-8f);
    float wyp = Y / (Z + 1e-8f);
    top4cells(wxp, wyp, &g_nbr[(size_t)t*16 + q*4]);
}

// ---------------- K3: bf16 m16n8k16 GEMM + fused per-split top-4 ------------
// Block: 128 rows x 128 cols, 8 warps (2x4), warp tile 64x32.
// Smem tiles [128][RSTRIDE=72 bf16] (144B rows, cols 0..63 used per chunk),
// fragment LDS banks (4g+tig)%32 -> conflict-free. B is pre-normalized so
// epilogue is sim = 2 - 2*acc, with running min-4 per row + penalty bitmask.
__global__ __launch_bounds__(256) void k_gemm_bf16() {
    __shared__ union {
        struct { __nv_bfloat16 A[128*RSTRIDE]; __nv_bfloat16 B[128*RSTRIDE]; } ld;
        float red[128][64];
    } sm;
    __shared__ uint32_t mask[128][4];

    int bm = blockIdx.x, bn = blockIdx.y, b = blockIdx.z;
    int tid = threadIdx.x;
    int lane = tid & 31, warp = tid >> 5;
    int wy = warp & 1, wx = warp >> 1;      // 2 x 4 warp grid
    int wrow = wy * 64, wcol = wx * 32;
    int g = lane >> 2, tig = lane & 3;
    int n0 = bn * 128, m0 = bm * 128;
    const __nv_bfloat16* A  = g_kdb + (size_t)b*Nq*Cq;
    const __nv_bfloat16* Bt = g_d2b + (size_t)b*MPAD*Cq;

    // penalty bitmask for this block's 128 rows x 128 local cols
    if (tid < 128) { mask[tid][0] = 0; mask[tid][1] = 0; mask[tid][2] = 0; mask[tid][3] = 0; }
    __syncthreads();
    {
        int row = tid >> 1;
        int qb  = (tid & 1) * 8;
        const int* nb = &g_nbr[(size_t)(b*Nq + n0 + row)*16];
        #pragma unroll
        for (int q = 0; q < 8; q++) {
            int loc = nb[qb + q] - m0;
            if (loc >= 0 && loc < 128)
                atomicOr(&mask[row][loc >> 5], 1u << (loc & 31));
        }
    }

    float c[4][4][4];
    #pragma unroll
    for (int mt = 0; mt < 4; mt++)
        #pragma unroll
        for (int nt = 0; nt < 4; nt++)
            #pragma unroll
            for (int r = 0; r < 4; r++) c[mt][nt][r] = 0.f;

    __syncthreads();
    for (int kc = 0; kc < 4; kc++) {       // K chunks of 64
        #pragma unroll
        for (int h = 0; h < 4; h++) {
            int idx = tid + h*256;         // 0..1023
            int row = idx >> 3;            // 0..127
            int c16 = idx & 7;             // 16B sub-chunk within 128B
            uint4 va = *(const uint4*)&A [(size_t)(n0 + row)*Cq + kc*64 + c16*8];
            uint4 vb = *(const uint4*)&Bt[(size_t)(m0 + row)*Cq + kc*64 + c16*8];
            *(uint4*)((char*)sm.ld.A + row*144 + c16*16) = va;
            *(uint4*)((char*)sm.ld.B + row*144 + c16*16) = vb;
        }
        __syncthreads();
        #pragma unroll
        for (int ks = 0; ks < 4; ks++) {   // k-steps of 16
            int sk = ks * 16;
            uint32_t af[4][4], bf[4][2];
            #pragma unroll
            for (int mt = 0; mt < 4; mt++) {
                int rb = wrow + mt*16 + g;
                const char* baseA = (const char*)sm.ld.A;
                af[mt][0] = *(const uint32_t*)(baseA + rb*144     + (sk + 2*tig)*2);
                af[mt][1] = *(const uint32_t*)(baseA + (rb+8)*144 + (sk + 2*tig)*2);
                af[mt][2] = *(const uint32_t*)(baseA + rb*144     + (sk + 2*tig + 8)*2);
                af[mt][3] = *(const uint32_t*)(baseA + (rb+8)*144 + (sk + 2*tig + 8)*2);
            }
            #pragma unroll
            for (int nt = 0; nt < 4; nt++) {
                int cb = wcol + nt*8 + g;
                const char* baseB = (const char*)sm.ld.B;
                bf[nt][0] = *(const uint32_t*)(baseB + cb*144 + (sk + 2*tig)*2);
                bf[nt][1] = *(const uint32_t*)(baseB + cb*144 + (sk + 2*tig + 8)*2);
            }
            #pragma unroll
            for (int mt = 0; mt < 4; mt++)
                #pragma unroll
                for (int nt = 0; nt < 4; nt++) {
                    asm volatile(
                        "mma.sync.aligned.m16n8k16.row.col.f32.bf16.bf16.f32 "
                        "{%0,%1,%2,%3}, {%4,%5,%6,%7}, {%8,%9}, {%0,%1,%2,%3};"
                        : "+f"(c[mt][nt][0]), "+f"(c[mt][nt][1]),
                          "+f"(c[mt][nt][2]), "+f"(c[mt][nt][3])
                        : "r"(af[mt][0]), "r"(af[mt][1]), "r"(af[mt][2]), "r"(af[mt][3]),
                          "r"(bf[nt][0]), "r"(bf[nt][1]));
                }
        }
        __syncthreads();
    }

    // ---- epilogue: per-thread running top-4 per row (sim = 2 - 2*acc) ----
    float t4[8][4];
    #pragma unroll
    for (int r = 0; r < 8; r++)
        #pragma unroll
        for (int s = 0; s < 4; s++) t4[r][s] = 1e30f;

    #pragma unroll
    for (int nt = 0; nt < 4; nt++) {
        int coll = wcol + nt*8 + tig*2;       // local col (even)
        int colg = m0 + coll;
        bool ok0 = colg < HWq, ok1 = (colg + 1) < HWq;
        #pragma unroll
        for (int mt = 0; mt < 4; mt++) {
            int lr0 = wrow + mt*16 + g;
            int lr1 = lr0 + 8;
            float v00 = 2.f - 2.f*c[mt][nt][0];
            float v01 = 2.f - 2.f*c[mt][nt][1];
            float v10 = 2.f - 2.f*c[mt][nt][2];
            float v11 = 2.f - 2.f*c[mt][nt][3];
            uint32_t m0b0 = mask[lr0][coll >> 5], m0b1 = mask[lr0][(coll+1) >> 5];
            uint32_t m1b0 = mask[lr1][coll >> 5], m1b1 = mask[lr1][(coll+1) >> 5];
            if (ok0 && !((m0b0 >> (coll & 31)) & 1))       ins4(t4[mt*2],     v00);
            if (ok1 && !((m0b1 >> ((coll+1) & 31)) & 1))   ins4(t4[mt*2],     v01);
            if (ok0 && !((m1b0 >> (coll & 31)) & 1))       ins4(t4[mt*2 + 1], v10);
            if (ok1 && !((m1b1 >> ((coll+1) & 31)) & 1))   ins4(t4[mt*2 + 1], v11);
        }
    }

    // ---- block reduction: 16 threads x 4 candidates -> top-4 per row ----
    __syncthreads();   // ld union dead, red live
    #pragma unroll
    for (int mt = 0; mt < 4; mt++) {
        int lr0 = wrow + mt*16 + g;
        int slot = (wx*4 + tig) * 4;
        *(float4*)&sm.red[lr0    ][slot] = *(float4*)t4[mt*2];
        *(float4*)&sm.red[lr0 + 8][slot] = *(float4*)t4[mt*2 + 1];
    }
    __syncthreads();
    if (tid < 128) {
        float tt[4] = {1e30f, 1e30f, 1e30f, 1e30f};
        const float* r = sm.red[tid];
        #pragma unroll 8
        for (int q = 0; q < 64; q++) ins4(tt, r[q]);
        *(float4*)&g_part[((size_t)(b*Nq + n0 + tid)*NSPLIT + bm)*4] =
            make_float4(tt[0], tt[1], tt[2], tt[3]);
    }
}

// ---------------- K4: merge per-split partials, hinge ----------------------
__global__ void k_merge() {
    int row = blockIdx.x * 4 + (threadIdx.x >> 5);   // 4 warps/block
    int lane = threadIdx.x & 31;
    const float* p = &g_part[(size_t)row*NSPLIT*4];
    float t[4] = {1e30f, 1e30f, 1e30f, 1e30f};
    for (int i = lane; i < NSPLIT*4; i += 32) ins4(t, p[i]);
    #pragma unroll
    for (int off = 16; off > 0; off >>= 1) {
        float o0 = __shfl_xor_sync(0xffffffffu, t[0], off);
        float o1 = __shfl_xor_sync(0xffffffffu, t[1], off);
        float o2 = __shfl_xor_sync(0xffffffffu, t[2], off);
        float o3 = __shfl_xor_sync(0xffffffffu, t[3], off);
        float a[4] = {t[0], t[1], t[2], t[3]};
        float o[4] = {o0, o1, o2, o3};
        int ia = 0, ib = 0;
        #pragma unroll
        for (int k = 0; k < 4; k++) {
            float av = (ia < 4) ? a[ia] : 1e30f;
            float bv = (ib < 4) ? o[ib] : 1e30f;
            if (av <= bv) { t[k] = av; ia++; } else { t[k] = bv; ib++; }
        }
    }
    if (lane == 0) {
        float pos = g_pos[row];
        float lsum = 0.f;
        #pragma unroll
        for (int r = 0; r < 4; r++) lsum += fmaxf(pos - t[r] + 1.0f, 0.f);
        g_rowloss[row] = lsum;
    }
}

// ---------------- K5: deterministic final mean ------------------------------
__global__ void k_final(float* out) {
    __shared__ float red[256];
    int tid = threadIdx.x;
    float acc = 0.f;
    for (int i = tid; i < Bq*Nq; i += 256) acc += g_rowloss[i];
    red[tid] = acc; __syncthreads();
    for (int s = 128; s > 0; s >>= 1) {
        if (tid < s) red[tid] += red[tid + s];
        __syncthreads();
    }
    if (tid == 0) out[0] = red[0] / (float)(Bq*Nq*NUM_NEG);
}

// ---------------- launch ----------------------------------------------------
extern "C" void kernel_launch(void* const* d_in, const int* in_sizes, int n_in,
                              void* d_out, int out_size) {
    const float* kp1      = (const float*)d_in[0];
    const float* w_kp1    = (const float*)d_in[1];
    const float* kp1_desc = (const float*)d_in[2];
    const float* desc2    = (const float*)d_in[3];
    const float* homo     = (const float*)d_in[4];
    float* out = (float*)d_out;

    k_norms<<<(Bq*HWq + 255)/256, 256>>>(desc2);
    k_transpose<<<dim3(HWq/32, Cq/32, Bq), dim3(32, 8)>>>(desc2);
    k_kd_pos<<<Bq*Nq, 256>>>(kp1_desc, w_kp1);
    k_d2b<<<(Bq*MPAD*Cq/4 + 255)/256, 256>>>();
    k_nbr<<<(Bq*Nq*4 + 127)/128, 128>>>(kp1, homo);
    k_gemm_bf16<<<dim3(NSPLIT, Nq/128, Bq), 256>>>();
    k_merge<<<Bq*Nq/4, 128>>>();
    k_final<<<1, 256>>>(out);
}

// round 9
// speedup vs baseline: 3.2527x; 1.1512x over previous
#include <cuda_runtime.h>
#include <cuda_bf16.h>
#include <math.h>
#include <stdint.h>

#define Bq 4
#define Nq 1024
#define Cq 256
#define Hq 60
#define Wq 80
#define HWq (Hq*Wq)          // 4800
#define GS 8.0f
#define NUM_NEG 4
#define NSPLIT 38            // ceil(4800/128) col splits
#define MPAD (NSPLIT*128)    // 4864 padded cols
#define TILEB 18432          // 128 rows * 144B
#define SMEM_GEMM (4*TILEB)  // A0,B0,A1,B1 = 73728 B

// ---------------- scratch (device globals; no allocs allowed) ----------------
__device__ float g_d2t[Bq*HWq*Cq];            // raw desc2 transposed [b][m][c]
__device__ __nv_bfloat16 g_kdb[Bq*Nq*Cq];     // normalized kp1 desc, bf16
__device__ __nv_bfloat16 g_d2b[Bq*MPAD*Cq];   // normalized desc2, bf16, padded
__device__ float g_pos[Bq*Nq];
__device__ int   g_nbr[Bq*Nq*16];             // 16 penalized cell ids per row
__device__ float g_part[Bq*Nq*NSPLIT*4];      // per-split partial top-4
__device__ float g_rowloss[Bq*Nq];

// ---------------- helpers ----------------
__device__ __forceinline__ float block_sum256(float v, float* red) {
    int t = threadIdx.x;
    red[t] = v; __syncthreads();
    #pragma unroll
    for (int s = 128; s > 0; s >>= 1) {
        if (t < s) red[t] += red[t + s];
        __syncthreads();
    }
    float r = red[0]; __syncthreads();
    return r;
}

__device__ __forceinline__ void ins4(float* t, float v) {
    if (v < t[3]) {
        if (v < t[2]) {
            t[3] = t[2];
            if (v < t[1]) { t[2] = t[1]; if (v < t[0]) { t[1] = t[0]; t[0] = v; } else t[1] = v; }
            else t[2] = v;
        } else t[3] = v;
    }
}

__device__ __forceinline__ uint32_t s2u(const void* p) {
    uint32_t a;
    asm("{ .reg .u64 t; cvta.to.shared.u64 t, %1; cvt.u32.u64 %0, t; }" : "=r"(a) : "l"(p));
    return a;
}
__device__ __forceinline__ void cpa16(uint32_t dst, const void* src) {
    asm volatile("cp.async.cg.shared.global [%0], [%1], 16;" :: "r"(dst), "l"(src));
}
__device__ __forceinline__ void ldsm_x4(uint32_t* r, uint32_t addr) {
    asm volatile("ldmatrix.sync.aligned.m8n8.x4.shared.b16 {%0,%1,%2,%3}, [%4];"
                 : "=r"(r[0]), "=r"(r[1]), "=r"(r[2]), "=r"(r[3]) : "r"(addr));
}

// 4 nearest grid centers to (px,py), replicating reference distance formula
// with lower-index tie-break.  Nearest 4 lattice centers always lie inside a
// clamped 5x5 window around floor(p/8).
__device__ void top4cells(float px, float py, int* out) {
    int cx0 = (int)floorf(px * 0.125f);
    int cy0 = (int)floorf(py * 0.125f);
    int lx = min(max(cx0 - 2, 0), Wq - 5);
    int ly = min(max(cy0 - 2, 0), Hq - 5);
    float bd0 = 1e30f, bd1 = 1e30f, bd2 = 1e30f, bd3 = 1e30f;
    int   bi0 = -1, bi1 = -1, bi2 = -1, bi3 = -1;
    float aa = px*px + py*py;
    for (int yy = ly; yy < ly + 5; yy++) {
        float cy = (yy + 0.5f) * GS;
        for (int xx = lx; xx < lx + 5; xx++) {
            float cx = (xx + 0.5f) * GS;
            float bb = cx*cx + cy*cy;
            float ab = px*cx + py*cy;
            float d = sqrtf(fmaxf(aa + bb - 2.0f*ab, 1e-12f));
            int id = yy * Wq + xx;
            if (d < bd3) {
                if (d < bd2) {
                    bd3 = bd2; bi3 = bi2;
                    if (d < bd1) {
                        bd2 = bd1; bi2 = bi1;
                        if (d < bd0) { bd1 = bd0; bi1 = bi0; bd0 = d; bi0 = id; }
                        else         { bd1 = d; bi1 = id; }
                    } else { bd2 = d; bi2 = id; }
                } else { bd3 = d; bi3 = id; }
            }
        }
    }
    out[0] = bi0; out[1] = bi1; out[2] = bi2; out[3] = bi3;
}

// ---------------- K1: fused norms + transpose + bf16 normalize --------------
// One block = 32 m-cells x 256 channels.  Reads desc2 tile once, computes
// per-cell norms in-block, writes fp32 transpose (for bilinear pos) and
// normalized bf16 (GEMM operand, zero-padded to MPAD rows).
__global__ void k_prep(const float* __restrict__ desc2) {
    __shared__ float tile[256][33];
    __shared__ float part[8][33];
    __shared__ float sinv[32];
    int b = blockIdx.y;
    int m0 = blockIdx.x * 32;
    int tid = threadIdx.x;

    if (m0 >= HWq) {     // padding rows of g_d2b -> zeros
        for (int i = tid; i < 32*Cq/2; i += 256) {
            int r = i / (Cq/2), c2 = i % (Cq/2);
            *(uint32_t*)&g_d2b[((size_t)b*MPAD + m0 + r)*Cq + c2*2] = 0u;
        }
        return;
    }

    int tx = tid & 31, ty = tid >> 5;
    #pragma unroll 8
    for (int q = 0; q < 32; q++) {
        int c = q*8 + ty;
        tile[c][tx] = desc2[((size_t)b*Cq + c)*HWq + m0 + tx];
    }
    __syncthreads();
    float ss = 0.f;
    #pragma unroll
    for (int i = 0; i < 32; i++) { float v = tile[ty*32 + i][tx]; ss += v*v; }
    part[ty][tx] = ss;
    __syncthreads();
    if (tid < 32) {
        float tot = 0.f;
        #pragma unroll
        for (int j = 0; j < 8; j++) tot += part[j][tid];
        sinv[tid] = 1.0f / sqrtf(tot + 1e-8f);
    }
    __syncthreads();
    #pragma unroll 4
    for (int r = 0; r < 32; r++) {
        float v = tile[tid][r];
        g_d2t[((size_t)b*HWq + m0 + r)*Cq + tid] = v;
        g_d2b[((size_t)b*MPAD + m0 + r)*Cq + tid] = __float2bfloat16(v * sinv[r]);
    }
}

// ---------------- K0: normalize kd (store bf16) + bilinear pos (fp32) -------
__global__ void k_kd_pos(const float* __restrict__ kp1_desc,
                         const float* __restrict__ w_kp1) {
    __shared__ float red[256];
    int row = blockIdx.x;               // b*N + n
    int b = row / Nq;
    int c = threadIdx.x;

    float v = kp1_desc[(size_t)row*Cq + c];
    float ss = block_sum256(v*v, red);
    float kd = v / sqrtf(ss + 1e-8f);
    g_kdb[(size_t)row*Cq + c] = __float2bfloat16(kd);

    float x = w_kp1[row*2 + 0] * 0.125f - 0.5f;
    float y = w_kp1[row*2 + 1] * 0.125f - 0.5f;
    float fx = floorf(x), fy = floorf(y);
    float wx = x - fx, wy = y - fy;
    int x0 = min(max((int)fx, 0), Wq - 1);
    int x1 = min(x0 + 1, Wq - 1);
    int y0 = min(max((int)fy, 0), Hq - 1);
    int y1 = min(y0 + 1, Hq - 1);
    const float* D = g_d2t + (size_t)b*HWq*Cq;
    float d00 = D[(size_t)(y0*Wq + x0)*Cq + c];
    float d01 = D[(size_t)(y0*Wq + x1)*Cq + c];
    float d10 = D[(size_t)(y1*Wq + x0)*Cq + c];
    float d11 = D[(size_t)(y1*Wq + x1)*Cq + c];
    float top = d00*(1.f - wx) + d01*wx;
    float bot = d10*(1.f - wx) + d11*wx;
    float wv = top*(1.f - wy) + bot*wy;

    float ws = block_sum256(wv*wv, red);
    float wn = wv / sqrtf(ws + 1e-8f);
    float dot = block_sum256(kd*wn, red);
    if (c == 0) g_pos[row] = 2.0f - 2.0f*dot;
}

// ---------------- K2: neighbourhood cell ids (one thread per (point, q)) ----
__global__ void k_nbr(const float* __restrict__ kp1,
                      const float* __restrict__ homo) {
    int idx = blockIdx.x * blockDim.x + threadIdx.x;
    if (idx >= Bq*Nq*4) return;
    int t = idx >> 2, q = idx & 3;
    int b = t / Nq;
    float px = kp1[t*2], py = kp1[t*2 + 1];
    const float* Hm = homo + b*9;
    int idx4[4];
    top4cells(px, py, idx4);
    int ci = idx4[q];
    int iy = ci / Wq, ix = ci % Wq;
    float cx = (ix + 0.5f)*GS, cy = (iy + 0.5f)*GS;
    float X = Hm[0]*cx + Hm[1]*cy + Hm[2];
    float Y = Hm[3]*cx + Hm[4]*cy + Hm[5];
    float Z = Hm[6]*cx + Hm[7]*cy + Hm[8];
    float wxp = X / (Z + 1e-8f);
    float wyp = Y / (Z + 1e-8f);
    top4cells(wxp, wyp, &g_nbr[(size_t)t*16 + q*4]);
}

// ---------------- K3: bf16 m16n8k16 GEMM, cp.async 2-stage, ldmatrix --------
// Block 128 rows x 128 cols, 8 warps (2x4), warp tile 64x32.
// Dynamic smem: A0,B0,A1,B1 tiles of 128 rows x 144B (rows 16B-aligned,
// 144B stride -> ldmatrix & cp.async conflict-free).  Fused top-4 epilogue.
__global__ __launch_bounds__(256, 2) void k_gemm_bf16() {
    extern __shared__ char dsm[];
    __shared__ uint32_t mask[128][4];
    uint32_t sbase = s2u(dsm);

    int bm = blockIdx.x, bn = blockIdx.y, b = blockIdx.z;
    int tid = threadIdx.x;
    int lane = tid & 31, warp = tid >> 5;
    int wy = warp & 1, wx = warp >> 1;      // 2 x 4 warp grid
    int wrow = wy * 64, wcol = wx * 32;
    int g = lane >> 2, tig = lane & 3;
    int n0 = bn * 128, m0 = bm * 128;
    const __nv_bfloat16* A  = g_kdb + (size_t)b*Nq*Cq;
    const __nv_bfloat16* Bt = g_d2b + (size_t)b*MPAD*Cq;

    int crow = tid >> 3, c16 = tid & 7;     // copy mapping (x4 rows per h)
    // prefetch both buffers up-front
    #pragma unroll
    for (int kc = 0; kc < 2; kc++) {
        uint32_t aT = sbase + kc*2*TILEB;
        uint32_t bT = aT + TILEB;
        #pragma unroll
        for (int h = 0; h < 4; h++) {
            int row = crow + h*32;
            cpa16(aT + row*144 + c16*16, &A [(size_t)(n0 + row)*Cq + kc*64 + c16*8]);
            cpa16(bT + row*144 + c16*16, &Bt[(size_t)(m0 + row)*Cq + kc*64 + c16*8]);
        }
        asm volatile("cp.async.commit_group;" ::: "memory");
    }

    // penalty bitmask for this block's 128 rows x 128 local cols
    if (tid < 128) { mask[tid][0] = 0; mask[tid][1] = 0; mask[tid][2] = 0; mask[tid][3] = 0; }
    __syncthreads();
    {
        int row = tid >> 1;
        int qb  = (tid & 1) * 8;
        const int* nb = &g_nbr[(size_t)(b*Nq + n0 + row)*16];
        #pragma unroll
        for (int q = 0; q < 8; q++) {
            int loc = nb[qb + q] - m0;
            if (loc >= 0 && loc < 128)
                atomicOr(&mask[row][loc >> 5], 1u << (loc & 31));
        }
    }

    float c[4][4][4];
    #pragma unroll
    for (int mt = 0; mt < 4; mt++)
        #pragma unroll
        for (int nt = 0; nt < 4; nt++)
            #pragma unroll
            for (int r = 0; r < 4; r++) c[mt][nt][r] = 0.f;

    for (int kc = 0; kc < 4; kc++) {
        if (kc < 3) asm volatile("cp.async.wait_group 1;" ::: "memory");
        else        asm volatile("cp.async.wait_group 0;" ::: "memory");
        __syncthreads();
        int buf = kc & 1;
        uint32_t aB = sbase + buf*2*TILEB;
        uint32_t bB = aB + TILEB;
        #pragma unroll
        for (int ks = 0; ks < 4; ks++) {
            int sk = ks * 16;
            uint32_t af[4][4], bf[4][2];
            #pragma unroll
            for (int mt = 0; mt < 4; mt++)
                ldsm_x4(af[mt], aB + (wrow + mt*16 + (lane & 15))*144
                                   + (sk + ((lane >> 4) << 3))*2);
            #pragma unroll
            for (int p = 0; p < 2; p++) {
                int mi = lane >> 3;
                int ntl = p*2 + (mi >> 1);
                int kh = mi & 1;
                uint32_t r[4];
                ldsm_x4(r, bB + (wcol + ntl*8 + (lane & 7))*144 + (sk + kh*8)*2);
                bf[p*2][0] = r[0]; bf[p*2][1] = r[1];
                bf[p*2+1][0] = r[2]; bf[p*2+1][1] = r[3];
            }
            #pragma unroll
            for (int mt = 0; mt < 4; mt++)
                #pragma unroll
                for (int nt = 0; nt < 4; nt++) {
                    asm volatile(
                        "mma.sync.aligned.m16n8k16.row.col.f32.bf16.bf16.f32 "
                        "{%0,%1,%2,%3}, {%4,%5,%6,%7}, {%8,%9}, {%0,%1,%2,%3};"
                        : "+f"(c[mt][nt][0]), "+f"(c[mt][nt][1]),
                          "+f"(c[mt][nt][2]), "+f"(c[mt][nt][3])
                        : "r"(af[mt][0]), "r"(af[mt][1]), "r"(af[mt][2]), "r"(af[mt][3]),
                          "r"(bf[nt][0]), "r"(bf[nt][1]));
                }
        }
        __syncthreads();
        if (kc + 2 < 4) {   // refill the buffer just consumed
            uint32_t aT = sbase + buf*2*TILEB;
            uint32_t bT = aT + TILEB;
            #pragma unroll
            for (int h = 0; h < 4; h++) {
                int row = crow + h*32;
                cpa16(aT + row*144 + c16*16, &A [(size_t)(n0 + row)*Cq + (kc+2)*64 + c16*8]);
                cpa16(bT + row*144 + c16*16, &Bt[(size_t)(m0 + row)*Cq + (kc+2)*64 + c16*8]);
            }
            asm volatile("cp.async.commit_group;" ::: "memory");
        }
    }

    // ---- epilogue: per-thread running top-4 per row (sim = 2 - 2*acc) ----
    float t4[8][4];
    #pragma unroll
    for (int r = 0; r < 8; r++)
        #pragma unroll
        for (int s = 0; s < 4; s++) t4[r][s] = 1e30f;

    #pragma unroll
    for (int nt = 0; nt < 4; nt++) {
        int coll = wcol + nt*8 + tig*2;       // local col (even)
        int colg = m0 + coll;
        bool ok0 = colg < HWq, ok1 = (colg + 1) < HWq;
        #pragma unroll
        for (int mt = 0; mt < 4; mt++) {
            int lr0 = wrow + mt*16 + g;
            int lr1 = lr0 + 8;
            float v00 = 2.f - 2.f*c[mt][nt][0];
            float v01 = 2.f - 2.f*c[mt][nt][1];
            float v10 = 2.f - 2.f*c[mt][nt][2];
            float v11 = 2.f - 2.f*c[mt][nt][3];
            uint32_t m0b0 = mask[lr0][coll >> 5], m0b1 = mask[lr0][(coll+1) >> 5];
            uint32_t m1b0 = mask[lr1][coll >> 5], m1b1 = mask[lr1][(coll+1) >> 5];
            if (ok0 && !((m0b0 >> (coll & 31)) & 1))       ins4(t4[mt*2],     v00);
            if (ok1 && !((m0b1 >> ((coll+1) & 31)) & 1))   ins4(t4[mt*2],     v01);
            if (ok0 && !((m1b0 >> (coll & 31)) & 1))       ins4(t4[mt*2 + 1], v10);
            if (ok1 && !((m1b1 >> ((coll+1) & 31)) & 1))   ins4(t4[mt*2 + 1], v11);
        }
    }

    // ---- block reduction in reused dynamic smem: 64 cands -> top-4 per row --
    float* red = (float*)dsm;   // [128][64]
    __syncthreads();
    #pragma unroll
    for (int mt = 0; mt < 4; mt++) {
        int lr0 = wrow + mt*16 + g;
        int slot = (wx*4 + tig) * 4;
        *(float4*)&red[(lr0    )*64 + slot] = *(float4*)t4[mt*2];
        *(float4*)&red[(lr0 + 8)*64 + slot] = *(float4*)t4[mt*2 + 1];
    }
    __syncthreads();
    if (tid < 128) {
        float tt[4] = {1e30f, 1e30f, 1e30f, 1e30f};
        const float* r = &red[tid*64];
        #pragma unroll 8
        for (int q = 0; q < 64; q++) ins4(tt, r[q]);
        *(float4*)&g_part[((size_t)(b*Nq + n0 + tid)*NSPLIT + bm)*4] =
            make_float4(tt[0], tt[1], tt[2], tt[3]);
    }
}

// ---------------- K4: merge per-split partials, hinge ----------------------
__global__ void k_merge() {
    int row = blockIdx.x * 4 + (threadIdx.x >> 5);   // 4 warps/block
    int lane = threadIdx.x & 31;
    const float* p = &g_part[(size_t)row*NSPLIT*4];
    float t[4] = {1e30f, 1e30f, 1e30f, 1e30f};
    for (int i = lane; i < NSPLIT*4; i += 32) ins4(t, p[i]);
    #pragma unroll
    for (int off = 16; off > 0; off >>= 1) {
        float o0 = __shfl_xor_sync(0xffffffffu, t[0], off);
        float o1 = __shfl_xor_sync(0xffffffffu, t[1], off);
        float o2 = __shfl_xor_sync(0xffffffffu, t[2], off);
        float o3 = __shfl_xor_sync(0xffffffffu, t[3], off);
        float a[4] = {t[0], t[1], t[2], t[3]};
        float o[4] = {o0, o1, o2, o3};
        int ia = 0, ib = 0;
        #pragma unroll
        for (int k = 0; k < 4; k++) {
            float av = (ia < 4) ? a[ia] : 1e30f;
            float bv = (ib < 4) ? o[ib] : 1e30f;
            if (av <= bv) { t[k] = av; ia++; } else { t[k] = bv; ib++; }
        }
    }
    if (lane == 0) {
        float pos = g_pos[row];
        float lsum = 0.f;
        #pragma unroll
        for (int r = 0; r < 4; r++) lsum += fmaxf(pos - t[r] + 1.0f, 0.f);
        g_rowloss[row] = lsum;
    }
}

// ---------------- K5: deterministic final mean ------------------------------
__global__ void k_final(float* out) {
    __shared__ float red[256];
    int tid = threadIdx.x;
    float acc = 0.f;
    for (int i = tid; i < Bq*Nq; i += 256) acc += g_rowloss[i];
    red[tid] = acc; __syncthreads();
    for (int s = 128; s > 0; s >>= 1) {
        if (tid < s) red[tid] += red[tid + s];
        __syncthreads();
    }
    if (tid == 0) out[0] = red[0] / (float)(Bq*Nq*NUM_NEG);
}

// ---------------- launch ----------------------------------------------------
extern "C" void kernel_launch(void* const* d_in, const int* in_sizes, int n_in,
                              void* d_out, int out_size) {
    const float* kp1      = (const float*)d_in[0];
    const float* w_kp1    = (const float*)d_in[1];
    const float* kp1_desc = (const float*)d_in[2];
    const float* desc2    = (const float*)d_in[3];
    const float* homo     = (const float*)d_in[4];
    float* out = (float*)d_out;

    cudaFuncSetAttribute(k_gemm_bf16, cudaFuncAttributeMaxDynamicSharedMemorySize, SMEM_GEMM);

    k_prep<<<dim3(MPAD/32, Bq), 256>>>(desc2);
    k_kd_pos<<<Bq*Nq, 256>>>(kp1_desc, w_kp1);
    k_nbr<<<(Bq*Nq*4)/64, 64>>>(kp1, homo);
    k_gemm_bf16<<<dim3(NSPLIT, Nq/128, Bq), 256, SMEM_GEMM>>>();
    k_merge<<<Bq*Nq/4, 128>>>();
    k_final<<<1, 256>>>(out);
}